// round 3
// baseline (speedup 1.0000x reference)
#include <cuda_runtime.h>
#include <stdint.h>

#define BATCH 64
#define NV    100000
#define NF    200000
#define NADJ  (6 * NF)
#define SCAN_THREADS 1024

// -------- device scratch (static allocations only; no cudaMalloc allowed) ----
__device__ int   g_deg[NV];          // degree per vertex (== reference deg)
__device__ int   g_off[NV + 1];      // CSR offsets
__device__ int   g_cur[NV];          // fill cursors
__device__ int   g_adj[NADJ];        // CSR adjacency (neighbor vertex ids)
// verts transposed: [v][c][b]  (c = xyz component, b = batch)
// per-vertex stride = 3*64 floats = 768 B (multiple of 128 B -> aligned lines)
__device__ float g_vt[(size_t)NV * 3 * BATCH];

// ---------------------------------------------------------------- K0: zero ---
__global__ void k_zero(float* out) {
    int t = blockIdx.x * blockDim.x + threadIdx.x;
    if (t < NV) g_deg[t] = 0;
    if (t == 0) out[0] = 0.0f;
}

// ------------------------------------------------------------- K1: degrees ---
// faces are int32 on device (JAX default x64-disabled downcasts int64->int32)
__global__ void k_count(const int* __restrict__ faces) {
    int f = blockIdx.x * blockDim.x + threadIdx.x;
    if (f >= NF) return;
    int i = faces[3 * f + 0];
    int j = faces[3 * f + 1];
    int k = faces[3 * f + 2];
    // per face, the reference src list contains each of i,j,k exactly twice
    atomicAdd(&g_deg[i], 2);
    atomicAdd(&g_deg[j], 2);
    atomicAdd(&g_deg[k], 2);
}

// ------------------------------------------------- K2: exclusive prefix scan --
__global__ void k_scan() {
    __shared__ int sh[SCAN_THREADS];
    const int t = threadIdx.x;
    const int chunk = (NV + SCAN_THREADS - 1) / SCAN_THREADS;  // 98
    int lo = t * chunk;
    int hi = lo + chunk; if (hi > NV) hi = NV;
    if (lo > NV) lo = NV;

    int s = 0;
    for (int i = lo; i < hi; ++i) s += g_deg[i];
    sh[t] = s;
    __syncthreads();

    for (int ofs = 1; ofs < SCAN_THREADS; ofs <<= 1) {
        int v = (t >= ofs) ? sh[t - ofs] : 0;
        __syncthreads();
        sh[t] += v;
        __syncthreads();
    }

    int run = (t == 0) ? 0 : sh[t - 1];
    for (int i = lo; i < hi; ++i) {
        g_off[i] = run;
        g_cur[i] = run;
        run += g_deg[i];
    }
    if (t == SCAN_THREADS - 1) g_off[NV] = sh[SCAN_THREADS - 1];
}

// ------------------------------------------------------------ K3: fill CSR ---
__global__ void k_fill(const int* __restrict__ faces) {
    int f = blockIdx.x * blockDim.x + threadIdx.x;
    if (f >= NF) return;
    int i = faces[3 * f + 0];
    int j = faces[3 * f + 1];
    int k = faces[3 * f + 2];
    int p;
    p = atomicAdd(&g_cur[i], 2); g_adj[p] = j; g_adj[p + 1] = k;
    p = atomicAdd(&g_cur[j], 2); g_adj[p] = i; g_adj[p + 1] = k;
    p = atomicAdd(&g_cur[k], 2); g_adj[p] = j; g_adj[p + 1] = i;
}

// ----------------------------------------------------------- K4: transpose ---
// verts[b][v][c]  ->  g_vt[v][c][b]
__global__ void k_transpose(const float* __restrict__ verts) {
    int t = blockIdx.x * blockDim.x + threadIdx.x;
    if (t >= BATCH * NV) return;
    int b = t / NV;
    int v = t - b * NV;       // consecutive lanes -> consecutive v: coalesced reads
    const float* src = verts + (size_t)b * NV * 3 + (size_t)v * 3;
    float x = src[0], y = src[1], z = src[2];
    float* dst = g_vt + (size_t)v * (3 * BATCH) + b;
    dst[0 * BATCH] = x;
    dst[1 * BATCH] = y;
    dst[2 * BATCH] = z;
}

// ------------------------------------------------------------- K5: gather ----
// thread = (v, b); v = t>>6, b = t&63. A warp lies fully within one v, so the
// adjacency read is a warp-uniform broadcast and each component read is one
// fully-utilized, 128B-aligned cache line per warp.
__global__ void k_main(float* __restrict__ out) {
    const int t = blockIdx.x * blockDim.x + threadIdx.x;
    float pv = 0.0f;

    if (t < BATCH * NV) {
        const int v = t >> 6;
        const int b = t & 63;

        const int s = g_off[v];
        const int d = g_deg[v];

        float a0 = 0.f, a1 = 0.f, a2 = 0.f;
        #pragma unroll 4
        for (int e = 0; e < d; ++e) {
            int n = __ldg(&g_adj[s + e]);
            const float* p = g_vt + (size_t)n * (3 * BATCH) + b;
            a0 += __ldg(p + 0 * BATCH);
            a1 += __ldg(p + 1 * BATCH);
            a2 += __ldg(p + 2 * BATCH);
        }

        const float* pvtx = g_vt + (size_t)v * (3 * BATCH) + b;
        float fd  = (d > 0) ? (float)d : 1.0f;
        float inv = 1.0f / fd;
        float l0 = __ldg(pvtx + 0 * BATCH) - a0 * inv;
        float l1 = __ldg(pvtx + 1 * BATCH) - a1 * inv;
        float l2 = __ldg(pvtx + 2 * BATCH) - a2 * inv;
        pv = sqrtf(l0 * l0 + l1 * l1 + l2 * l2);
    }

    // block reduction: warp shuffle then shared
    #pragma unroll
    for (int ofs = 16; ofs > 0; ofs >>= 1)
        pv += __shfl_down_sync(0xFFFFFFFFu, pv, ofs);

    __shared__ float wsum[8];
    int lane = threadIdx.x & 31;
    int wid  = threadIdx.x >> 5;
    if (lane == 0) wsum[wid] = pv;
    __syncthreads();
    if (threadIdx.x == 0) {
        float s = 0.f;
        #pragma unroll
        for (int w = 0; w < 8; ++w) s += wsum[w];
        atomicAdd(out, s * (1.0f / ((float)BATCH * (float)NV)));
    }
}

// -----------------------------------------------------------------------------
extern "C" void kernel_launch(void* const* d_in, const int* in_sizes, int n_in,
                              void* d_out, int out_size) {
    const float* verts = (const float*)d_in[0];
    const int*   faces = (const int*)d_in[1];
    float*       out   = (float*)d_out;

    k_zero<<<(NV + 255) / 256, 256>>>(out);
    k_count<<<(NF + 255) / 256, 256>>>(faces);
    k_scan<<<1, SCAN_THREADS>>>();
    k_fill<<<(NF + 255) / 256, 256>>>(faces);
    k_transpose<<<(BATCH * NV + 255) / 256, 256>>>(verts);
    k_main<<<(BATCH * NV + 255) / 256, 256>>>(out);
}

// round 13
// speedup vs baseline: 2.9525x; 2.9525x over previous
#include <cuda_runtime.h>
#include <stdint.h>

#define BATCH 64
#define NV    100000
#define NF    200000
#define NADJ  (6 * NF)
#define NBLK  391          // ceil(NV / 256)

// -------- device scratch (static allocations only) ---------------------------
__device__ int    g_deg[NV];
__device__ int    g_off[NV];
__device__ int    g_cur[NV];
__device__ int    g_adj[NADJ];
__device__ int    g_bsum[NBLK];
__device__ int    g_boff[NBLK];
// verts transposed: [v][c][b] as float4 units: vertex stride 48 float4 (768B)
__device__ float4 g_vt4[(size_t)NV * 48];

// ---------------------------------------------------------------- K0: zero ---
__global__ void k_zero(float* out) {
    int t = blockIdx.x * blockDim.x + threadIdx.x;
    if (t < NV) g_deg[t] = 0;
    if (t == 0) out[0] = 0.0f;
}

// ------------------------------------------------------------- K1: degrees ---
__global__ void k_count(const int* __restrict__ faces) {
    int f = blockIdx.x * blockDim.x + threadIdx.x;
    if (f >= NF) return;
    int i = faces[3 * f + 0];
    int j = faces[3 * f + 1];
    int k = faces[3 * f + 2];
    atomicAdd(&g_deg[i], 2);
    atomicAdd(&g_deg[j], 2);
    atomicAdd(&g_deg[k], 2);
}

// --------------------------------------------- K2a: per-block degree sums ----
__global__ void k_s1() {
    __shared__ int sh[256];
    int i = blockIdx.x * 256 + threadIdx.x;
    sh[threadIdx.x] = (i < NV) ? g_deg[i] : 0;
    __syncthreads();
    #pragma unroll
    for (int o = 128; o > 0; o >>= 1) {
        if (threadIdx.x < o) sh[threadIdx.x] += sh[threadIdx.x + o];
        __syncthreads();
    }
    if (threadIdx.x == 0) g_bsum[blockIdx.x] = sh[0];
}

// --------------------------------------------- K2b: scan 391 block sums ------
__global__ void k_s2() {
    __shared__ int sh[512];
    int t = threadIdx.x;
    sh[t] = (t < NBLK) ? g_bsum[t] : 0;
    __syncthreads();
    for (int o = 1; o < 512; o <<= 1) {
        int v = (t >= o) ? sh[t - o] : 0;
        __syncthreads();
        sh[t] += v;
        __syncthreads();
    }
    if (t < NBLK) g_boff[t] = (t == 0) ? 0 : sh[t - 1];
}

// --------------------------------------------- K2c: per-block exclusive scan -
__global__ void k_s3() {
    __shared__ int sh[256];
    int t = threadIdx.x;
    int i = blockIdx.x * 256 + t;
    int d = (i < NV) ? g_deg[i] : 0;
    sh[t] = d;
    __syncthreads();
    for (int o = 1; o < 256; o <<= 1) {
        int v = (t >= o) ? sh[t - o] : 0;
        __syncthreads();
        sh[t] += v;
        __syncthreads();
    }
    if (i < NV) {
        int excl = sh[t] - d + g_boff[blockIdx.x];
        g_off[i] = excl;
        g_cur[i] = excl;
    }
}

// ------------------------------------------------------------ K3: fill CSR ---
__global__ void k_fill(const int* __restrict__ faces) {
    int f = blockIdx.x * blockDim.x + threadIdx.x;
    if (f >= NF) return;
    int i = faces[3 * f + 0];
    int j = faces[3 * f + 1];
    int k = faces[3 * f + 2];
    int p;
    p = atomicAdd(&g_cur[i], 2); g_adj[p] = j; g_adj[p + 1] = k;
    p = atomicAdd(&g_cur[j], 2); g_adj[p] = i; g_adj[p + 1] = k;
    p = atomicAdd(&g_cur[k], 2); g_adj[p] = j; g_adj[p + 1] = i;
}

// ----------------------------------------------------------- K4: transpose ---
// verts[b][v][c] -> g_vt[v][c][b].  Lane layout: (4 v) x (8 b) so each
// (v,c) write covers 8 consecutive batches = one full 32B sector (no write
// amplification); reads are 48B-contiguous runs per b (~70% sector use).
__global__ void k_transpose(const float* __restrict__ verts) {
    int t = blockIdx.x * blockDim.x + threadIdx.x;
    if (t >= BATCH * NV) return;
    int v_lo = (t >> 3) & 3;
    int b_lo = t & 7;
    int u    = t >> 5;
    int b_hi = u & 7;
    int v_hi = u >> 3;            // 0..24999 (NV/4)
    int v = v_hi * 4 + v_lo;
    int b = b_hi * 8 + b_lo;
    const float* src = verts + (size_t)b * NV * 3 + (size_t)v * 3;
    float x = src[0], y = src[1], z = src[2];
    float* dst = (float*)g_vt4 + (size_t)v * 192 + b;
    dst[0]   = x;
    dst[64]  = y;
    dst[128] = z;
}

// ------------------------------------------------------------- K5: gather ----
// thread = (v, q), q in [0,16): handles 4 batches via float4 loads.
// 16 threads per v -> half-warp-uniform adjacency broadcast; each component
// load is 16 lanes x 16B = 256B contiguous (2 full lines).
__global__ void k_main(float* __restrict__ out) {
    const int t = blockIdx.x * blockDim.x + threadIdx.x;
    float pv = 0.0f;

    if (t < NV * 16) {
        const int v = t >> 4;
        const int q = t & 15;

        const int s = g_off[v];
        const int d = g_deg[v];

        float4 a0 = make_float4(0.f, 0.f, 0.f, 0.f);
        float4 a1 = a0, a2 = a0;

        #pragma unroll 4
        for (int e = 0; e < d; ++e) {
            int n = __ldg(&g_adj[s + e]);
            const float4* p = g_vt4 + (size_t)n * 48 + q;
            float4 x = __ldg(p);
            float4 y = __ldg(p + 16);
            float4 z = __ldg(p + 32);
            a0.x += x.x; a0.y += x.y; a0.z += x.z; a0.w += x.w;
            a1.x += y.x; a1.y += y.y; a1.z += y.z; a1.w += y.w;
            a2.x += z.x; a2.y += z.y; a2.z += z.z; a2.w += z.w;
        }

        const float4* pm = g_vt4 + (size_t)v * 48 + q;
        float4 m0 = __ldg(pm), m1 = __ldg(pm + 16), m2 = __ldg(pm + 32);

        float inv = 1.0f / ((d > 0) ? (float)d : 1.0f);

        float lx, ly, lz;
        lx = m0.x - a0.x * inv; ly = m1.x - a1.x * inv; lz = m2.x - a2.x * inv;
        pv += sqrtf(lx * lx + ly * ly + lz * lz);
        lx = m0.y - a0.y * inv; ly = m1.y - a1.y * inv; lz = m2.y - a2.y * inv;
        pv += sqrtf(lx * lx + ly * ly + lz * lz);
        lx = m0.z - a0.z * inv; ly = m1.z - a1.z * inv; lz = m2.z - a2.z * inv;
        pv += sqrtf(lx * lx + ly * ly + lz * lz);
        lx = m0.w - a0.w * inv; ly = m1.w - a1.w * inv; lz = m2.w - a2.w * inv;
        pv += sqrtf(lx * lx + ly * ly + lz * lz);
    }

    #pragma unroll
    for (int ofs = 16; ofs > 0; ofs >>= 1)
        pv += __shfl_down_sync(0xFFFFFFFFu, pv, ofs);

    __shared__ float wsum[8];
    int lane = threadIdx.x & 31;
    int wid  = threadIdx.x >> 5;
    if (lane == 0) wsum[wid] = pv;
    __syncthreads();
    if (threadIdx.x == 0) {
        float s = 0.f;
        #pragma unroll
        for (int w = 0; w < 8; ++w) s += wsum[w];
        atomicAdd(out, s * (1.0f / ((float)BATCH * (float)NV)));
    }
}

// -----------------------------------------------------------------------------
extern "C" void kernel_launch(void* const* d_in, const int* in_sizes, int n_in,
                              void* d_out, int out_size) {
    const float* verts = (const float*)d_in[0];
    const int*   faces = (const int*)d_in[1];
    float*       out   = (float*)d_out;

    k_zero     <<<(NV + 255) / 256, 256>>>(out);
    k_count    <<<(NF + 255) / 256, 256>>>(faces);
    k_s1       <<<NBLK, 256>>>();
    k_s2       <<<1, 512>>>();
    k_s3       <<<NBLK, 256>>>();
    k_fill     <<<(NF + 255) / 256, 256>>>(faces);
    k_transpose<<<(BATCH * NV) / 256, 256>>>(verts);
    k_main     <<<(NV * 16 + 255) / 256, 256>>>(out);
}